// round 11
// baseline (speedup 1.0000x reference)
#include <cuda_runtime.h>
#include <cuda_fp16.h>
#include <cstdint>

// ---------------- problem constants ----------------
#define B_ROWS   8192
#define DFEAT    128
#define DKEEP    64
#define TILE     128
#define NTILES   64
#define NTHREADS 512

#define LOG2E 1.4426950408889634f
#define LN2   0.6931471805599453f
#define SHIFTB 32.0f

// smem byte offsets (dynamic smem)
#define SB_X     0
#define SB_Y0    16384
#define SB_Y1    32768
#define SB_RSUM(q) (49152 + 512*(q))   // 4 x float[128]
#define SB_WRED  (49152+2048)          // float[4]
#define SMEM_BYTES (49152+2112)

// ---------------- scratch (fp16 gathered matrices) ----------------
__device__ __half g_ao [B_ROWS * DKEEP];  // a[:, ai]
__device__ __half g_iao[B_ROWS * DKEEP];  // v[:, ai]
__device__ __half g_io [B_ROWS * DKEEP];  // v[:, ii]
__device__ __half g_aio[B_ROWS * DKEEP];  // a[:, ii]

// ---------------- helpers ----------------
__device__ __forceinline__ uint32_t smem_u32(const void* p) {
    uint32_t a;
    asm("{ .reg .u64 t; cvta.to.shared.u64 t, %1; cvt.u32.u64 %0, t; }" : "=r"(a) : "l"(p));
    return a;
}

__device__ __forceinline__ void cp16(uint32_t dst, const void* src) {
    asm volatile("cp.async.cg.shared.global [%0], [%1], 16;" :: "r"(dst), "l"(src));
}
#define CP_COMMIT() asm volatile("cp.async.commit_group;" ::: "memory")
#define CP_WAIT(n)  asm volatile("cp.async.wait_group %0;" :: "n"(n) : "memory")

__device__ __forceinline__ void ldsm4(uint32_t r[4], uint32_t a) {
    asm volatile("ldmatrix.sync.aligned.m8n8.x4.shared.b16 {%0,%1,%2,%3}, [%4];"
        : "=r"(r[0]), "=r"(r[1]), "=r"(r[2]), "=r"(r[3]) : "r"(a));
}

// f32-accumulate MMA, D += A*B
__device__ __forceinline__ void mma16816_f(float c[4], const uint32_t a[4],
                                           uint32_t b0, uint32_t b1) {
    asm volatile(
        "mma.sync.aligned.m16n8k16.row.col.f32.f16.f16.f32 "
        "{%0,%1,%2,%3}, {%4,%5,%6,%7}, {%8,%9}, {%0,%1,%2,%3};"
        : "+f"(c[0]), "+f"(c[1]), "+f"(c[2]), "+f"(c[3])
        : "r"(a[0]), "r"(a[1]), "r"(a[2]), "r"(a[3]), "r"(b0), "r"(b1));
}

// f32-accumulate MMA, D = A*B + 0  (separate zero C -> no accumulator zeroing)
__device__ __forceinline__ void mma16816_fz(float d[4], const uint32_t a[4],
                                            uint32_t b0, uint32_t b1) {
    asm volatile(
        "mma.sync.aligned.m16n8k16.row.col.f32.f16.f16.f32 "
        "{%0,%1,%2,%3}, {%4,%5,%6,%7}, {%8,%9}, {%10,%10,%10,%10};"
        : "=f"(d[0]), "=f"(d[1]), "=f"(d[2]), "=f"(d[3])
        : "r"(a[0]), "r"(a[1]), "r"(a[2]), "r"(a[3]), "r"(b0), "r"(b1), "f"(0.0f));
}

__device__ __forceinline__ float ex2f(float t) {
    float e;
    asm("ex2.approx.ftz.f32 %0, %1;" : "=f"(e) : "f"(t));
    return e;
}

// exp-accumulate one f32 c-fragment: rows (r0 -> pa), (r0+8 -> pb)
__device__ __forceinline__ void exp_frag(const float (&v)[4], float& pa, float& pb) {
    pa += ex2f(fmaf(v[0], LOG2E, -SHIFTB));
    pa += ex2f(fmaf(v[1], LOG2E, -SHIFTB));
    pb += ex2f(fmaf(v[2], LOG2E, -SHIFTB));
    pb += ex2f(fmaf(v[3], LOG2E, -SHIFTB));
}

// compute tile into cur (32 rows x 32 cols per warp); exp-process prev,
// finely interleaved to co-feed tensor + MUFU pipes.
__device__ __forceinline__ void do_tile(
    uint32_t sbY,
    const uint32_t (&A)[2][4][4],
    const uint32_t (&browoff)[2], const uint32_t (&bxr)[2], int bko,
    float (&cur)[2][4][4], float (&prev)[2][4][4],
    float (&ps)[4])
{
#pragma unroll
    for (int kk = 0; kk < 4; kk++) {
        uint32_t Bf[2][4];
#pragma unroll
        for (int nn = 0; nn < 2; nn++) {
            uint32_t addr = sbY + browoff[nn] + (((uint32_t)((kk << 1) + bko) ^ bxr[nn]) << 4);
            ldsm4(Bf[nn], addr);
        }
        if (kk == 0) {
            mma16816_fz(cur[0][0], A[0][0], Bf[0][0], Bf[0][1]);
            mma16816_fz(cur[0][1], A[0][0], Bf[0][2], Bf[0][3]);
            exp_frag(prev[0][0], ps[0], ps[1]);
            mma16816_fz(cur[0][2], A[0][0], Bf[1][0], Bf[1][1]);
            mma16816_fz(cur[0][3], A[0][0], Bf[1][2], Bf[1][3]);
            mma16816_fz(cur[1][0], A[1][0], Bf[0][0], Bf[0][1]);
            exp_frag(prev[1][0], ps[2], ps[3]);
            mma16816_fz(cur[1][1], A[1][0], Bf[0][2], Bf[0][3]);
            mma16816_fz(cur[1][2], A[1][0], Bf[1][0], Bf[1][1]);
            mma16816_fz(cur[1][3], A[1][0], Bf[1][2], Bf[1][3]);
        } else {
            mma16816_f(cur[0][0], A[0][kk], Bf[0][0], Bf[0][1]);
            mma16816_f(cur[0][1], A[0][kk], Bf[0][2], Bf[0][3]);
            exp_frag(prev[0][kk], ps[0], ps[1]);
            mma16816_f(cur[0][2], A[0][kk], Bf[1][0], Bf[1][1]);
            mma16816_f(cur[0][3], A[0][kk], Bf[1][2], Bf[1][3]);
            mma16816_f(cur[1][0], A[1][kk], Bf[0][0], Bf[0][1]);
            exp_frag(prev[1][kk], ps[2], ps[3]);
            mma16816_f(cur[1][1], A[1][kk], Bf[0][2], Bf[0][3]);
            mma16816_f(cur[1][2], A[1][kk], Bf[1][0], Bf[1][1]);
            mma16816_f(cur[1][3], A[1][kk], Bf[1][2], Bf[1][3]);
        }
    }
}

// ---------------- kernels ----------------
// Index buffers may be int32 (JAX x64 disabled) or int64. Sniff: if every odd
// int32 word of BOTH buffers' first 64 words is zero, values are int64
// (indices < 128 => high words 0). Reads stay within 256B = in-bounds for both
// interpretations. Indices masked &127 so a misdetect can never fault.
__global__ void gather_kernel(const float* __restrict__ a, const float* __restrict__ v,
                              const int* __restrict__ ai32,
                              const int* __restrict__ ii32,
                              float* __restrict__ out, int out_size) {
    __shared__ int sai[DKEEP], sii[DKEEP];
    __shared__ int is64;
    const int tid = threadIdx.x;
    if (blockIdx.x == 0 && tid < out_size) out[tid] = 0.0f;  // fold zero_out
    if (tid == 0) {
        int orr = 0;
#pragma unroll
        for (int k = 0; k < 32; k++) orr |= ai32[2 * k + 1] | ii32[2 * k + 1];
        is64 = (orr == 0) ? 1 : 0;
    }
    __syncthreads();
    if (tid < DKEEP) {
        int step = is64 ? 2 : 1;
        sai[tid] = ai32[tid * step] & (DFEAT - 1);
        sii[tid] = ii32[tid * step] & (DFEAT - 1);
    }
    __syncthreads();

    int t = blockIdx.x * blockDim.x + tid;
    int r = t >> 6, k = t & 63;
    int ia = sai[k];
    int iv = sii[k];
    const float* ar = a + (size_t)r * DFEAT;
    const float* vr = v + (size_t)r * DFEAT;
    g_ao [t] = __float2half(ar[ia]);
    g_iao[t] = __float2half(vr[ia]);
    g_io [t] = __float2half(vr[iv]);
    g_aio[t] = __float2half(ar[iv]);
}

__global__ void __launch_bounds__(NTHREADS, 1)
supcon_main_kernel(float* __restrict__ out) {
    extern __shared__ char smem[];
    const uint32_t sb = smem_u32(smem);
    const int tid  = threadIdx.x;
    const int lane = tid & 31;
    const int wid  = tid >> 5;
    const int rg   = wid & 3;        // row group: rows 32*rg .. 32*rg+31
    const int cq   = wid >> 2;       // column quarter: cols 32*cq .. 32*cq+31
    const int m  = blockIdx.x >> 6;  // 0: S_v, 1: S_a
    const int rt = blockIdx.x & 63;  // row tile

    const __half* X = m ? g_aio : g_iao;
    const __half* Y = m ? g_io  : g_ao;
    const char* Yb = (const char*)Y;

    // per-thread swizzled 16B-chunk store offsets (u = tid + k*512)
    uint32_t dsto[2];
#pragma unroll
    for (int k = 0; k < 2; k++) {
        uint32_t u = (uint32_t)tid + k * 512u;
        dsto[k] = (u & ~7u) * 16u + (((u & 7u) ^ ((u >> 3) & 7u)) << 4);
    }

    // prefetch Y tiles 0, 1 via cp.async
#pragma unroll
    for (int k = 0; k < 2; k++)
        cp16(sb + SB_Y0 + dsto[k], Yb + (size_t)(tid + k * 512) * 16);
    CP_COMMIT();
#pragma unroll
    for (int k = 0; k < 2; k++)
        cp16(sb + SB_Y1 + dsto[k], Yb + 16384 + (size_t)(tid + k * 512) * 16);
    CP_COMMIT();

    // X tile -> smem (swizzled)
    {
        const uint4* xg = (const uint4*)(X + (size_t)rt * TILE * DKEEP);
#pragma unroll
        for (int k = 0; k < 2; k++) {
            uint4 val = xg[tid + k * 512];
            *(uint4*)(smem + SB_X + dsto[k]) = val;
        }
    }
    __syncthreads();

    // A fragments: 2 row-blocks x 4 k-chunks, held for the whole kernel
    uint32_t A[2][4][4];
    {
        int kc = lane >> 4;  // 0/1 -> k halves
#pragma unroll
        for (int rb = 0; rb < 2; rb++) {
            int row = 32 * rg + 16 * rb + (lane & 15);
#pragma unroll
            for (int kk = 0; kk < 4; kk++) {
                uint32_t chunk = (uint32_t)(kk * 2 + kc);
                uint32_t addr  = sb + SB_X + (uint32_t)row * 128u + ((chunk ^ (uint32_t)(row & 7)) << 4);
                ldsm4(A[rb][kk], addr);
            }
        }
    }

    // B ldmatrix address row parts (2 n-blocks of 16 cols in this warp's quarter)
    uint32_t browoff[2], bxr[2];
    const int bn  = ((lane >> 4) << 3) + (lane & 7);
    const int bko = (lane >> 3) & 1;
#pragma unroll
    for (int nn = 0; nn < 2; nn++) {
        int nr = 16 * (2 * cq + nn) + bn;
        browoff[nn] = (uint32_t)nr * 128u;
        bxr[nn] = (uint32_t)(nr & 7);
    }

    float accC[2][4][4], accP[2][4][4];
#pragma unroll
    for (int rb = 0; rb < 2; rb++)
#pragma unroll
        for (int f = 0; f < 4; f++)
#pragma unroll
            for (int c = 0; c < 4; c++) accP[rb][f][c] = -1e30f;  // exp -> 0 first tile
    float ps[4] = {0.f, 0.f, 0.f, 0.f};

    for (int jj = 0; jj < NTILES; jj += 2) {
        // ---- even tile jj : stage 0, cur=accC, prev=accP ----
        CP_WAIT(1);
        __syncthreads();
        do_tile(sb + SB_Y0, A, browoff, bxr, bko, accC, accP, ps);
        __syncthreads();
        if (jj + 2 < NTILES) {
            const char* src = Yb + (size_t)(jj + 2) * 16384;
#pragma unroll
            for (int k = 0; k < 2; k++)
                cp16(sb + SB_Y0 + dsto[k], src + (size_t)(tid + k * 512) * 16);
            CP_COMMIT();
        }
        // ---- odd tile jj+1 : stage 1, cur=accP, prev=accC ----
        if (jj + 1 == NTILES - 1) { CP_WAIT(0); } else { CP_WAIT(1); }
        __syncthreads();
        do_tile(sb + SB_Y1, A, browoff, bxr, bko, accP, accC, ps);
        __syncthreads();
        if (jj + 3 < NTILES) {
            const char* src = Yb + (size_t)(jj + 3) * 16384;
#pragma unroll
            for (int k = 0; k < 2; k++)
                cp16(sb + SB_Y1 + dsto[k], src + (size_t)(tid + k * 512) * 16);
            CP_COMMIT();
        }
    }

    // tail: exp-process the last tile (63, sitting in accP)
#pragma unroll
    for (int f = 0; f < 4; f++) {
        exp_frag(accP[0][f], ps[0], ps[1]);
        exp_frag(accP[1][f], ps[2], ps[3]);
    }

    // ---- reduction: quarter-row sums into smem planes ----
#pragma unroll
    for (int o = 1; o < 4; o <<= 1) {
        ps[0] += __shfl_xor_sync(0xffffffffu, ps[0], o);
        ps[1] += __shfl_xor_sync(0xffffffffu, ps[1], o);
        ps[2] += __shfl_xor_sync(0xffffffffu, ps[2], o);
        ps[3] += __shfl_xor_sync(0xffffffffu, ps[3], o);
    }
    const int r0 = 32 * rg + (lane >> 2);
    float* rsum = (float*)(smem + SB_RSUM(cq));
    if ((lane & 3) == 0) {
        rsum[r0]      = ps[0];
        rsum[r0 + 8]  = ps[1];
        rsum[r0 + 16] = ps[2];
        rsum[r0 + 24] = ps[3];
    }
    __syncthreads();

    // ---- diag recompute (f32) + final loss ----
    float loss = 0.f;
    if (tid < 128) {
        const uint4* xr = (const uint4*)(X + (size_t)(rt * TILE + tid) * DKEEP);
        const uint4* yr = (const uint4*)(Y + (size_t)(rt * TILE + tid) * DKEEP);
        float dg = 0.f;
#pragma unroll
        for (int i = 0; i < 8; i++) {
            uint4 xv = xr[i];
            uint4 yv = yr[i];
            const uint32_t* xw = (const uint32_t*)&xv;
            const uint32_t* yw = (const uint32_t*)&yv;
#pragma unroll
            for (int w = 0; w < 4; w++) {
                float2 xf = __half22float2(*(const __half2*)&xw[w]);
                float2 yf = __half22float2(*(const __half2*)&yw[w]);
                dg = fmaf(xf.x, yf.x, dg);
                dg = fmaf(xf.y, yf.y, dg);
            }
        }
        float tot = ((float*)(smem + SB_RSUM(0)))[tid] + ((float*)(smem + SB_RSUM(1)))[tid]
                  + ((float*)(smem + SB_RSUM(2)))[tid] + ((float*)(smem + SB_RSUM(3)))[tid];
        float lg;
        asm("lg2.approx.f32 %0, %1;" : "=f"(lg) : "f"(tot));
        loss = (lg + SHIFTB) * LN2 - dg;
#pragma unroll
        for (int o = 1; o < 32; o <<= 1)
            loss += __shfl_xor_sync(0xffffffffu, loss, o);
        if (lane == 0) ((float*)(smem + SB_WRED))[wid] = loss;
    }
    __syncthreads();
    if (tid == 0) {
        float* wr = (float*)(smem + SB_WRED);
        atomicAdd(out, (wr[0] + wr[1] + wr[2] + wr[3]) * (1.0f / (float)B_ROWS));
    }
}

// ---------------- launch ----------------
extern "C" void kernel_launch(void* const* d_in, const int* in_sizes, int n_in,
                              void* d_out, int out_size) {
    const float* a = (const float*)d_in[0];
    const float* v = (const float*)d_in[1];
    const int* ai = (const int*)d_in[2];
    const int* ii = (const int*)d_in[3];
    float* out = (float*)d_out;

    cudaFuncSetAttribute(supcon_main_kernel,
                         cudaFuncAttributeMaxDynamicSharedMemorySize, SMEM_BYTES);

    gather_kernel<<<(B_ROWS * DKEEP) / 256, 256>>>(a, v, ai, ii, out, out_size);
    supcon_main_kernel<<<128, NTHREADS, SMEM_BYTES>>>(out);
}

// round 12
// speedup vs baseline: 1.0980x; 1.0980x over previous
#include <cuda_runtime.h>
#include <cuda_fp16.h>
#include <cstdint>

// ---------------- problem constants ----------------
#define B_ROWS   8192
#define DFEAT    128
#define DKEEP    64
#define TILE     128
#define NTILES   64
#define NTHREADS 256

#define LOG2E 1.4426950408889634f
#define LN2   0.6931471805599453f
#define SHIFTB 32.0f

// smem byte offsets (dynamic smem)
#define SB_X     0
#define SB_Y0    16384
#define SB_Y1    32768
#define SB_RSUM0 49152            // float[128]
#define SB_RSUM1 (49152+512)
#define SB_WRED  (49152+1024)     // float[4]
#define SMEM_BYTES (49152+1088)

// ---------------- scratch (fp16 gathered matrices) ----------------
__device__ __half g_ao [B_ROWS * DKEEP];  // a[:, ai]
__device__ __half g_iao[B_ROWS * DKEEP];  // v[:, ai]
__device__ __half g_io [B_ROWS * DKEEP];  // v[:, ii]
__device__ __half g_aio[B_ROWS * DKEEP];  // a[:, ii]

// ---------------- helpers ----------------
__device__ __forceinline__ uint32_t smem_u32(const void* p) {
    uint32_t a;
    asm("{ .reg .u64 t; cvta.to.shared.u64 t, %1; cvt.u32.u64 %0, t; }" : "=r"(a) : "l"(p));
    return a;
}

__device__ __forceinline__ void cp16(uint32_t dst, const void* src) {
    asm volatile("cp.async.cg.shared.global [%0], [%1], 16;" :: "r"(dst), "l"(src));
}
#define CP_COMMIT() asm volatile("cp.async.commit_group;" ::: "memory")
#define CP_WAIT(n)  asm volatile("cp.async.wait_group %0;" :: "n"(n) : "memory")

__device__ __forceinline__ void ldsm4(uint32_t r[4], uint32_t a) {
    asm volatile("ldmatrix.sync.aligned.m8n8.x4.shared.b16 {%0,%1,%2,%3}, [%4];"
        : "=r"(r[0]), "=r"(r[1]), "=r"(r[2]), "=r"(r[3]) : "r"(a));
}

// f32-accumulate MMA, D += A*B
__device__ __forceinline__ void mma16816_f(float c[4], const uint32_t a[4],
                                           uint32_t b0, uint32_t b1) {
    asm volatile(
        "mma.sync.aligned.m16n8k16.row.col.f32.f16.f16.f32 "
        "{%0,%1,%2,%3}, {%4,%5,%6,%7}, {%8,%9}, {%0,%1,%2,%3};"
        : "+f"(c[0]), "+f"(c[1]), "+f"(c[2]), "+f"(c[3])
        : "r"(a[0]), "r"(a[1]), "r"(a[2]), "r"(a[3]), "r"(b0), "r"(b1));
}

__device__ __forceinline__ float ex2f(float t) {
    float e;
    asm("ex2.approx.ftz.f32 %0, %1;" : "=f"(e) : "f"(t));
    return e;
}

// exp-accumulate one f32 c-fragment (4 elements): pure FFMA + EX2 + FADD
__device__ __forceinline__ void exp_frag(const float (&v)[4], float& p0, float& p1,
                                         float& p2, float& p3) {
    p0 += ex2f(fmaf(v[0], LOG2E, -SHIFTB));
    p1 += ex2f(fmaf(v[1], LOG2E, -SHIFTB));
    p2 += ex2f(fmaf(v[2], LOG2E, -SHIFTB));
    p3 += ex2f(fmaf(v[3], LOG2E, -SHIFTB));
}

// compute tile into cur (32 rows x 64 cols per warp; 2 row-blocks share B frags);
// exp-process prev, finely interleaved. B fragments are double-buffered across
// k-steps: the ldsm pair for kk+1 issues early inside kk's MMA stream, hiding
// shared-memory latency behind ~20 MMAs + 16 ex2.
__device__ __forceinline__ void do_tile(
    uint32_t sbY,
    const uint32_t (&A)[2][4][4],
    const uint32_t (&browoff)[4], const uint32_t (&bxr)[4], int bko,
    float (&cur)[2][8][4], float (&prev)[2][8][4],
    float (&ps)[8])
{
#pragma unroll
    for (int rb = 0; rb < 2; rb++)
#pragma unroll
        for (int f = 0; f < 8; f++)
#pragma unroll
            for (int c = 0; c < 4; c++) cur[rb][f][c] = 0.f;

    uint32_t Bf[2][4][4];
    // preload k-step 0
#pragma unroll
    for (int nn = 0; nn < 4; nn++) {
        uint32_t addr = sbY + browoff[nn] + (((uint32_t)bko ^ bxr[nn]) << 4);
        ldsm4(Bf[0][nn], addr);
    }
#pragma unroll
    for (int kk = 0; kk < 4; kk++) {
        const int cb = kk & 1, nb = cb ^ 1;
        // row-block 0, n-blocks 0-1 + early prefetch of next k-step's B frags
        mma16816_f(cur[0][0], A[0][kk], Bf[cb][0][0], Bf[cb][0][1]);
        mma16816_f(cur[0][1], A[0][kk], Bf[cb][0][2], Bf[cb][0][3]);
        if (kk < 3) {
#pragma unroll
            for (int nn = 0; nn < 4; nn++) {
                uint32_t addr = sbY + browoff[nn]
                              + (((uint32_t)(((kk + 1) << 1) + bko) ^ bxr[nn]) << 4);
                ldsm4(Bf[nb][nn], addr);
            }
        }
        exp_frag(prev[0][2 * kk], ps[0], ps[1], ps[2], ps[3]);
        mma16816_f(cur[0][2], A[0][kk], Bf[cb][1][0], Bf[cb][1][1]);
        mma16816_f(cur[0][3], A[0][kk], Bf[cb][1][2], Bf[cb][1][3]);
        exp_frag(prev[0][2 * kk + 1], ps[0], ps[1], ps[2], ps[3]);
        mma16816_f(cur[0][4], A[0][kk], Bf[cb][2][0], Bf[cb][2][1]);
        mma16816_f(cur[0][5], A[0][kk], Bf[cb][2][2], Bf[cb][2][3]);
        exp_frag(prev[1][2 * kk], ps[4], ps[5], ps[6], ps[7]);
        mma16816_f(cur[0][6], A[0][kk], Bf[cb][3][0], Bf[cb][3][1]);
        mma16816_f(cur[0][7], A[0][kk], Bf[cb][3][2], Bf[cb][3][3]);
        exp_frag(prev[1][2 * kk + 1], ps[4], ps[5], ps[6], ps[7]);
        // row-block 1 (reuses the same B frags -> half the LDS traffic)
        mma16816_f(cur[1][0], A[1][kk], Bf[cb][0][0], Bf[cb][0][1]);
        mma16816_f(cur[1][1], A[1][kk], Bf[cb][0][2], Bf[cb][0][3]);
        mma16816_f(cur[1][2], A[1][kk], Bf[cb][1][0], Bf[cb][1][1]);
        mma16816_f(cur[1][3], A[1][kk], Bf[cb][1][2], Bf[cb][1][3]);
        mma16816_f(cur[1][4], A[1][kk], Bf[cb][2][0], Bf[cb][2][1]);
        mma16816_f(cur[1][5], A[1][kk], Bf[cb][2][2], Bf[cb][2][3]);
        mma16816_f(cur[1][6], A[1][kk], Bf[cb][3][0], Bf[cb][3][1]);
        mma16816_f(cur[1][7], A[1][kk], Bf[cb][3][2], Bf[cb][3][3]);
    }
}

// ---------------- kernels ----------------
// Index buffers may be int32 (JAX x64 disabled) or int64. Sniff: if every odd
// int32 word of BOTH buffers' first 64 words is zero, values are int64
// (indices < 128 => high words 0). Reads stay within 256B = in-bounds for both
// interpretations. Indices masked &127 so a misdetect can never fault.
__global__ void gather_kernel(const float* __restrict__ a, const float* __restrict__ v,
                              const int* __restrict__ ai32,
                              const int* __restrict__ ii32,
                              float* __restrict__ out, int out_size) {
    __shared__ int sai[DKEEP], sii[DKEEP];
    __shared__ int is64;
    const int tid = threadIdx.x;
    if (blockIdx.x == 0 && tid < out_size) out[tid] = 0.0f;  // fold zero_out
    if (tid == 0) {
        int orr = 0;
#pragma unroll
        for (int k = 0; k < 32; k++) orr |= ai32[2 * k + 1] | ii32[2 * k + 1];
        is64 = (orr == 0) ? 1 : 0;
    }
    __syncthreads();
    if (tid < DKEEP) {
        int step = is64 ? 2 : 1;
        sai[tid] = ai32[tid * step] & (DFEAT - 1);
        sii[tid] = ii32[tid * step] & (DFEAT - 1);
    }
    __syncthreads();

    int t = blockIdx.x * blockDim.x + tid;
    int r = t >> 6, k = t & 63;
    int ia = sai[k];
    int iv = sii[k];
    const float* ar = a + (size_t)r * DFEAT;
    const float* vr = v + (size_t)r * DFEAT;
    g_ao [t] = __float2half(ar[ia]);
    g_iao[t] = __float2half(vr[ia]);
    g_io [t] = __float2half(vr[iv]);
    g_aio[t] = __float2half(ar[iv]);
}

__global__ void __launch_bounds__(NTHREADS, 1)
supcon_main_kernel(float* __restrict__ out) {
    extern __shared__ char smem[];
    const uint32_t sb = smem_u32(smem);
    const int tid  = threadIdx.x;
    const int lane = tid & 31;
    const int wid  = tid >> 5;
    const int rg   = wid & 3;        // row group: rows 32*rg .. 32*rg+31
    const int ch   = wid >> 2;       // column half: cols 64*ch .. 64*ch+63
    const int m  = blockIdx.x >> 6;  // 0: S_v, 1: S_a
    const int rt = blockIdx.x & 63;  // row tile

    const __half* X = m ? g_aio : g_iao;
    const __half* Y = m ? g_io  : g_ao;
    const char* Yb = (const char*)Y;

    // per-thread swizzled 16B-chunk store offsets (u = tid + k*256)
    uint32_t dsto[4];
#pragma unroll
    for (int k = 0; k < 4; k++) {
        uint32_t u = (uint32_t)tid + k * 256u;
        dsto[k] = (u & ~7u) * 16u + (((u & 7u) ^ ((u >> 3) & 7u)) << 4);
    }

    // prefetch Y tiles 0, 1 via cp.async
#pragma unroll
    for (int k = 0; k < 4; k++)
        cp16(sb + SB_Y0 + dsto[k], Yb + (size_t)(tid + k * 256) * 16);
    CP_COMMIT();
#pragma unroll
    for (int k = 0; k < 4; k++)
        cp16(sb + SB_Y1 + dsto[k], Yb + 16384 + (size_t)(tid + k * 256) * 16);
    CP_COMMIT();

    // X tile -> smem (swizzled)
    {
        const uint4* xg = (const uint4*)(X + (size_t)rt * TILE * DKEEP);
#pragma unroll
        for (int k = 0; k < 4; k++) {
            uint4 val = xg[tid + k * 256];
            *(uint4*)(smem + SB_X + dsto[k]) = val;
        }
    }
    __syncthreads();

    // A fragments: 2 row-blocks x 4 k-chunks, held for the whole kernel
    uint32_t A[2][4][4];
    {
        int kc = lane >> 4;  // 0/1 -> k halves
#pragma unroll
        for (int rb = 0; rb < 2; rb++) {
            int row = 32 * rg + 16 * rb + (lane & 15);
#pragma unroll
            for (int kk = 0; kk < 4; kk++) {
                uint32_t chunk = (uint32_t)(kk * 2 + kc);
                uint32_t addr  = sb + SB_X + (uint32_t)row * 128u + ((chunk ^ (uint32_t)(row & 7)) << 4);
                ldsm4(A[rb][kk], addr);
            }
        }
    }

    // B ldmatrix address row parts (4 n-blocks of 16 cols in this warp's half)
    uint32_t browoff[4], bxr[4];
    const int bn  = ((lane >> 4) << 3) + (lane & 7);
    const int bko = (lane >> 3) & 1;
#pragma unroll
    for (int nn = 0; nn < 4; nn++) {
        int nr = 16 * (4 * ch + nn) + bn;
        browoff[nn] = (uint32_t)nr * 128u;
        bxr[nn] = (uint32_t)(nr & 7);
    }

    float accC[2][8][4], accP[2][8][4];
#pragma unroll
    for (int rb = 0; rb < 2; rb++)
#pragma unroll
        for (int f = 0; f < 8; f++)
#pragma unroll
            for (int c = 0; c < 4; c++) accP[rb][f][c] = -1e30f;  // exp -> 0 first tile
    float ps[8] = {0.f, 0.f, 0.f, 0.f, 0.f, 0.f, 0.f, 0.f};

    for (int jj = 0; jj < NTILES; jj += 2) {
        // ---- even tile jj : stage 0, cur=accC, prev=accP ----
        CP_WAIT(1);
        __syncthreads();
        do_tile(sb + SB_Y0, A, browoff, bxr, bko, accC, accP, ps);
        __syncthreads();
        if (jj + 2 < NTILES) {
            const char* src = Yb + (size_t)(jj + 2) * 16384;
#pragma unroll
            for (int k = 0; k < 4; k++)
                cp16(sb + SB_Y0 + dsto[k], src + (size_t)(tid + k * 256) * 16);
            CP_COMMIT();
        }
        // ---- odd tile jj+1 : stage 1, cur=accP, prev=accC ----
        if (jj + 1 == NTILES - 1) { CP_WAIT(0); } else { CP_WAIT(1); }
        __syncthreads();
        do_tile(sb + SB_Y1, A, browoff, bxr, bko, accP, accC, ps);
        __syncthreads();
        if (jj + 3 < NTILES) {
            const char* src = Yb + (size_t)(jj + 3) * 16384;
#pragma unroll
            for (int k = 0; k < 4; k++)
                cp16(sb + SB_Y1 + dsto[k], src + (size_t)(tid + k * 256) * 16);
            CP_COMMIT();
        }
    }

    // tail: exp-process the last tile (63, sitting in accP)
#pragma unroll
    for (int f = 0; f < 8; f++) {
        exp_frag(accP[0][f], ps[0], ps[1], ps[2], ps[3]);
        exp_frag(accP[1][f], ps[4], ps[5], ps[6], ps[7]);
    }

    // ---- reduction: half-row sums into smem planes ----
    float rsA0 = ps[0] + ps[1];            // rb0, row r0,    this 64-col half
    float rsA1 = ps[2] + ps[3];            // rb0, row r0+8
    float rsB0 = ps[4] + ps[5];            // rb1, row r0+16
    float rsB1 = ps[6] + ps[7];            // rb1, row r0+24
#pragma unroll
    for (int o = 1; o < 4; o <<= 1) {
        rsA0 += __shfl_xor_sync(0xffffffffu, rsA0, o);
        rsA1 += __shfl_xor_sync(0xffffffffu, rsA1, o);
        rsB0 += __shfl_xor_sync(0xffffffffu, rsB0, o);
        rsB1 += __shfl_xor_sync(0xffffffffu, rsB1, o);
    }

    const int r0 = 32 * rg + (lane >> 2);
    float* rsum = (float*)(smem + (ch ? SB_RSUM1 : SB_RSUM0));
    if ((lane & 3) == 0) {
        rsum[r0]      = rsA0;
        rsum[r0 + 8]  = rsA1;
        rsum[r0 + 16] = rsB0;
        rsum[r0 + 24] = rsB1;
    }
    __syncthreads();

    // ---- diag recompute (f32) + final loss ----
    float loss = 0.f;
    if (tid < 128) {
        const uint4* xr = (const uint4*)(X + (size_t)(rt * TILE + tid) * DKEEP);
        const uint4* yr = (const uint4*)(Y + (size_t)(rt * TILE + tid) * DKEEP);
        float dg = 0.f;
#pragma unroll
        for (int i = 0; i < 8; i++) {
            uint4 xv = xr[i];
            uint4 yv = yr[i];
            const uint32_t* xw = (const uint32_t*)&xv;
            const uint32_t* yw = (const uint32_t*)&yv;
#pragma unroll
            for (int w = 0; w < 4; w++) {
                float2 xf = __half22float2(*(const __half2*)&xw[w]);
                float2 yf = __half22float2(*(const __half2*)&yw[w]);
                dg = fmaf(xf.x, yf.x, dg);
                dg = fmaf(xf.y, yf.y, dg);
            }
        }
        float tot = ((float*)(smem + SB_RSUM0))[tid] + ((float*)(smem + SB_RSUM1))[tid];
        float lg;
        asm("lg2.approx.f32 %0, %1;" : "=f"(lg) : "f"(tot));
        loss = (lg + SHIFTB) * LN2 - dg;
#pragma unroll
        for (int o = 1; o < 32; o <<= 1)
            loss += __shfl_xor_sync(0xffffffffu, loss, o);
        if (lane == 0) ((float*)(smem + SB_WRED))[wid] = loss;
    }
    __syncthreads();
    if (tid == 0) {
        float* wr = (float*)(smem + SB_WRED);
        atomicAdd(out, (wr[0] + wr[1] + wr[2] + wr[3]) * (1.0f / (float)B_ROWS));
    }
}

// ---------------- launch ----------------
extern "C" void kernel_launch(void* const* d_in, const int* in_sizes, int n_in,
                              void* d_out, int out_size) {
    const float* a = (const float*)d_in[0];
    const float* v = (const float*)d_in[1];
    const int* ai = (const int*)d_in[2];
    const int* ii = (const int*)d_in[3];
    float* out = (float*)d_out;

    cudaFuncSetAttribute(supcon_main_kernel,
                         cudaFuncAttributeMaxDynamicSharedMemorySize, SMEM_BYTES);

    gather_kernel<<<(B_ROWS * DKEEP) / 256, 256>>>(a, v, ai, ii, out, out_size);
    supcon_main_kernel<<<128, NTHREADS, SMEM_BYTES>>>(out);
}